// round 8
// baseline (speedup 1.0000x reference)
#include <cuda_runtime.h>

// Problem constants (fixed by the dataset)
#define NQ 65536          // number of query vectors (32*2048)
#define NE 1024           // codebook entries
#define D  64             // embedding dim
#define BM 64             // queries per block
#define BN 128            // codes per chunk
#define NCH (NE / BN)     // 8 chunks

// smem strides (in floats)
#define ZST 136           // dup-z row stride: 64 q-pairs (128 floats) + 8 pad
#define EST 132           // e row stride: 128 codes + 4 pad

// Output layout: tuple (loss, z_q_st, perplexity, idx) flattened to float32
#define O_LOSS 0
#define O_ZQ   1
#define O_PERP (1 + NQ * D)
#define O_IDX  (2 + NQ * D)

__device__ float        g_e2[NE];
__device__ unsigned int g_counts[NE];
__device__ double       g_loss;
__device__ unsigned int g_done;

// ---------------------------------------------------------------------------
// prep: per-code ||e||^2 with reference rounding (separate mul+add, ascending
// k), parallel across 8 blocks x 128 threads; also resets counters.
// ---------------------------------------------------------------------------
__global__ void vq_prep(const float* __restrict__ cb) {
    int j = blockIdx.x * 128 + threadIdx.x;   // 0..1023
    const float4* r = (const float4*)(cb + (size_t)j * D);
    float4 v[16];
#pragma unroll
    for (int i = 0; i < 16; i++) v[i] = r[i];   // 16 independent LDG.128
    float s = 0.f;
#pragma unroll
    for (int i = 0; i < 16; i++) {
        s = __fadd_rn(s, __fmul_rn(v[i].x, v[i].x));
        s = __fadd_rn(s, __fmul_rn(v[i].y, v[i].y));
        s = __fadd_rn(s, __fmul_rn(v[i].z, v[i].z));
        s = __fadd_rn(s, __fmul_rn(v[i].w, v[i].w));
    }
    g_e2[j] = s;
    g_counts[j] = 0u;
    if (j == 0) { g_loss = 0.0; g_done = 0u; }
}

// ---------------------------------------------------------------------------
// packed fp32x2 helper (Blackwell FFMA2 — PTX-only path)
// ---------------------------------------------------------------------------
__device__ __forceinline__ unsigned long long fma2(unsigned long long a,
                                                   unsigned long long b,
                                                   unsigned long long c) {
    unsigned long long d;
    asm("fma.rn.f32x2 %0, %1, %2, %3;" : "=l"(d) : "l"(a), "l"(b), "l"(c));
    return d;
}

extern __shared__ float smem_dyn[];

// ---------------------------------------------------------------------------
// main: fused distance GEMM + argmin + gather + z_q_st + loss + (last CTA)
// perplexity finish.  grid = NQ/BM = 1024 CTAs of 256 threads, 2 CTAs/SM.
// smem: szd[D][ZST] (dup z pairs) + se[2][D][EST] + e2s[2][BN] = 103424 B.
// Pipeline: LDG chunk ch+1 into regs BEFORE compute of ch, STS AFTER.
// ---------------------------------------------------------------------------
__global__ void __launch_bounds__(256, 2)
vq_main(const float* __restrict__ z, const float* __restrict__ cb,
        float* __restrict__ out) {
    float* szd = smem_dyn;                         // [D][ZST] dup-z {z,z}
    float* se0 = smem_dyn + D * ZST;               // [D][EST] e buf 0
    float* se1 = smem_dyn + D * ZST + D * EST;     // [D][EST] e buf 1
    float* e2s = smem_dyn + D * ZST + 2 * D * EST; // [2][BN]
    __shared__ float szz[BM];
    __shared__ int   sbest[BM];
    __shared__ float swred[8];
    __shared__ unsigned int s_ticket;

    const int tid = threadIdx.x;
    const int tx  = tid & 15;        // 16 code-columns of threads
    const int ty  = tid >> 4;        // 16 query-rows of threads (4 q each)
    const int q0  = blockIdx.x * BM;

    // ---- prologue: z tile as duplicated pairs [k][q]{z,z} -------------------
    {
        const float4* zg = (const float4*)(z + (size_t)q0 * D);
#pragma unroll
        for (int i = 0; i < 4; i++) {
            int idx = i * 256 + tid;          // 0..1023
            int q   = idx >> 4;               // 0..63
            int kf  = idx & 15;               // float4 index along k
            float4 v = zg[q * 16 + kf];
            float2* p0 = (float2*)(szd + (kf * 4 + 0) * ZST + 2 * q);
            float2* p1 = (float2*)(szd + (kf * 4 + 1) * ZST + 2 * q);
            float2* p2 = (float2*)(szd + (kf * 4 + 2) * ZST + 2 * q);
            float2* p3 = (float2*)(szd + (kf * 4 + 3) * ZST + 2 * q);
            *p0 = make_float2(v.x, v.x);
            *p1 = make_float2(v.y, v.y);
            *p2 = make_float2(v.z, v.z);
            *p3 = make_float2(v.w, v.w);
        }
        // chunk 0 e tile: [k][j] (transposed during store)
        const float4* eg = (const float4*)(cb);
#pragma unroll
        for (int p = 0; p < 8; p++) {
            int j = p * 16 + ty;
            float4 v = eg[j * 16 + tx];
            se0[(tx * 4 + 0) * EST + j] = v.x;
            se0[(tx * 4 + 1) * EST + j] = v.y;
            se0[(tx * 4 + 2) * EST + j] = v.z;
            se0[(tx * 4 + 3) * EST + j] = v.w;
        }
        if (tid < BN) e2s[tid] = g_e2[tid];
    }
    __syncthreads();

    // ---- per-query ||z||^2, reference rounding (ascending k) ----------------
    if (tid < BM) {
        float s = 0.f;
#pragma unroll
        for (int k = 0; k < D; k++) {
            float v = szd[k * ZST + 2 * tid];
            s = __fadd_rn(s, __fmul_rn(v, v));
        }
        szz[tid] = s;
    }
    __syncthreads();

    float best[4];
    int   bidx[4];
#pragma unroll
    for (int i = 0; i < 4; i++) { best[i] = 3.4028235e38f; bidx[i] = 0; }

    for (int ch = 0; ch < NCH; ch++) {
        const int buf = ch & 1;
        const float* cur = buf ? se1 : se0;
        float* nxt = buf ? se0 : se1;

        // ---- prefetch chunk ch+1 into REGISTERS (no dependent store yet) ----
        float4 ev[8];
        float  e2v = 0.f;
        if (ch < NCH - 1) {
            const float4* eg = (const float4*)(cb + (size_t)(ch + 1) * BN * D);
#pragma unroll
            for (int p = 0; p < 8; p++)
                ev[p] = eg[(p * 16 + ty) * 16 + tx];
            if (tid < BN) e2v = g_e2[(ch + 1) * BN + tid];
        }

        // ---- compute: 4q x 8codes per thread, packed f32x2 ------------------
        // code pairs at 32-code stride: acc[qi][cp] <-> codes cp*32 + tx*2 {+0,+1}
        unsigned long long acc[4][4];
#pragma unroll
        for (int a = 0; a < 4; a++)
#pragma unroll
            for (int b = 0; b < 4; b++) acc[a][b] = 0ULL;

        const float* zp0 = szd + ty * 8;       // 4 q-pairs (u64) per thread
        const float* ep0 = cur + tx * 2;       // code pair tx*2 within group

#pragma unroll 4
        for (int k = 0; k < D; k++) {
            ulonglong2 zqa = *(const ulonglong2*)(zp0 + k * ZST);
            ulonglong2 zqb = *(const ulonglong2*)(zp0 + k * ZST + 4);
            unsigned long long zq[4];
            zq[0] = zqa.x; zq[1] = zqa.y; zq[2] = zqb.x; zq[3] = zqb.y;
            unsigned long long ep[4];
            ep[0] = *(const unsigned long long*)(ep0 + k * EST);
            ep[1] = *(const unsigned long long*)(ep0 + k * EST + 32);
            ep[2] = *(const unsigned long long*)(ep0 + k * EST + 64);
            ep[3] = *(const unsigned long long*)(ep0 + k * EST + 96);
#pragma unroll
            for (int qi = 0; qi < 4; qi++) {
                acc[qi][0] = fma2(zq[qi], ep[0], acc[qi][0]);
                acc[qi][1] = fma2(zq[qi], ep[1], acc[qi][1]);
                acc[qi][2] = fma2(zq[qi], ep[2], acc[qi][2]);
                acc[qi][3] = fma2(zq[qi], ep[3], acc[qi][3]);
            }
        }

        // ---- fold: s = fl(fl(zz+ee) - 2*dot), first-index argmin ------------
        // Within a thread j ascends (cp ascending, +0 before +1): strict <.
#pragma unroll
        for (int cp = 0; cp < 4; cp++) {
            int loc = cp * 32 + tx * 2;
            int jb  = ch * BN + loc;
            float2 e2p = *(const float2*)(e2s + buf * BN + loc);
#pragma unroll
            for (int qi = 0; qi < 4; qi++) {
                float zz = szz[ty * 4 + qi];
                float lo, hi;
                asm("mov.b64 {%0, %1}, %2;" : "=f"(lo), "=f"(hi) : "l"(acc[qi][cp]));
                float s0 = __fsub_rn(__fadd_rn(zz, e2p.x), 2.0f * lo);
                float s1 = __fsub_rn(__fadd_rn(zz, e2p.y), 2.0f * hi);
                if (s0 < best[qi]) { best[qi] = s0; bidx[qi] = jb; }
                if (s1 < best[qi]) { best[qi] = s1; bidx[qi] = jb + 1; }
            }
        }

        // ---- drain prefetch into the other buffer (data long since arrived) -
        if (ch < NCH - 1) {
#pragma unroll
            for (int p = 0; p < 8; p++) {
                int j = p * 16 + ty;
                nxt[(tx * 4 + 0) * EST + j] = ev[p].x;
                nxt[(tx * 4 + 1) * EST + j] = ev[p].y;
                nxt[(tx * 4 + 2) * EST + j] = ev[p].z;
                nxt[(tx * 4 + 3) * EST + j] = ev[p].w;
            }
            if (tid < BN) e2s[(buf ^ 1) * BN + tid] = e2v;
        }
        __syncthreads();
    }

    // ---- cross-thread argmin reduction (16 tx-cols per query) ---------------
    float* rs = se0;                       // overlay: [BM][16] scores
    int*   rj = (int*)(se0 + BM * 16);     //          [BM][16] indices
#pragma unroll
    for (int qi = 0; qi < 4; qi++) {
        int qrow = ty * 4 + qi;
        rs[qrow * 16 + tx] = best[qi];
        rj[qrow * 16 + tx] = bidx[qi];
    }
    __syncthreads();
    if (tid < BM) {
        float bs = rs[tid * 16];
        int   bj = rj[tid * 16];
#pragma unroll
        for (int r = 1; r < 16; r++) {
            float s = rs[tid * 16 + r];
            int   j = rj[tid * 16 + r];
            if (s < bs || (s == bs && j < bj)) { bs = s; bj = j; }
        }
        sbest[tid] = bj;
        out[O_IDX + q0 + tid] = (float)bj;
        atomicAdd(&g_counts[bj], 1u);
    }
    __syncthreads();

    // ---- epilogue: gather codebook, write z_q_st, accumulate loss -----------
    // out + O_ZQ is 4-byte-misaligned for float4 (O_ZQ == 1): scalar STG.32.
    float lsum = 0.f;
#pragma unroll
    for (int qi = 0; qi < 4; qi++) {
        int ql = ty * 4 + qi;
        int bj = sbest[ql];
        float4 cv = *(const float4*)(cb + (size_t)bj * D + tx * 4);
        float z0 = szd[(tx * 4 + 0) * ZST + 2 * ql];
        float z1 = szd[(tx * 4 + 1) * ZST + 2 * ql];
        float z2 = szd[(tx * 4 + 2) * ZST + 2 * ql];
        float z3 = szd[(tx * 4 + 3) * ZST + 2 * ql];
        float d0 = cv.x - z0, d1 = cv.y - z1, d2 = cv.z - z2, d3 = cv.w - z3;
        float* op = out + O_ZQ + (size_t)(q0 + ql) * D + tx * 4;
        op[0] = z0 + d0;
        op[1] = z1 + d1;
        op[2] = z2 + d2;
        op[3] = z3 + d3;
        lsum += d0 * d0 + d1 * d1 + d2 * d2 + d3 * d3;
    }
#pragma unroll
    for (int o = 16; o > 0; o >>= 1)
        lsum += __shfl_xor_sync(0xffffffffu, lsum, o);
    if ((tid & 31) == 0) swred[tid >> 5] = lsum;
    __syncthreads();
    if (tid == 0) {
        double t = 0.0;
#pragma unroll
        for (int w = 0; w < 8; w++) t += (double)swred[w];
        atomicAdd(&g_loss, t);
    }

    // ---- last-CTA finish: perplexity + loss scalar --------------------------
    __threadfence();
    __syncthreads();
    if (tid == 0) s_ticket = atomicAdd(&g_done, 1u);
    __syncthreads();
    if (s_ticket == (unsigned int)(gridDim.x - 1)) {
        float s = 0.f;
#pragma unroll
        for (int i = 0; i < 4; i++) {
            int t = i * 256 + tid;
            float em = __fmul_rn((float)g_counts[t], 1.0f / (float)NQ);
            s += em * logf(__fadd_rn(em, 1e-10f));
        }
#pragma unroll
        for (int o = 16; o > 0; o >>= 1)
            s += __shfl_xor_sync(0xffffffffu, s, o);
        if ((tid & 31) == 0) swred[tid >> 5] = s;
        __syncthreads();
        if (tid == 0) {
            float v = 0.f;
#pragma unroll
            for (int w = 0; w < 8; w++) v += swred[w];
            out[O_PERP] = expf(-v);
            out[O_LOSS] = (float)(g_loss * (1.25 / (double)((size_t)NQ * D)));
        }
    }
}

// ---------------------------------------------------------------------------
extern "C" void kernel_launch(void* const* d_in, const int* in_sizes, int n_in,
                              void* d_out, int out_size) {
    (void)in_sizes; (void)n_in; (void)out_size;
    const float* z  = (const float*)d_in[0];
    const float* cb = (const float*)d_in[1];
    float* out = (float*)d_out;

    static bool attr_done = false;   // host-side, capture-safe, deterministic
    const int smem = (D * ZST + 2 * D * EST + 2 * BN) * (int)sizeof(float); // 103424
    if (!attr_done) {
        cudaFuncSetAttribute(vq_main, cudaFuncAttributeMaxDynamicSharedMemorySize, smem);
        attr_done = true;
    }

    vq_prep<<<8, 128>>>(cb);
    vq_main<<<NQ / BM, 256, smem>>>(z, cb, out);
}